// round 5
// baseline (speedup 1.0000x reference)
#include <cuda_runtime.h>

// WideComponent: out[b] = emb_user[u[b]] + emb_item[i[b]] + emb_cat[c[b]]
//                       + cross_w[u[b]*D_CAT + c[b]]
//                       + cross_w[OFF_IC + i[b]*D_CAT + c[b]]
// D_USER=100000, D_ITEM=50000, D_CAT=1000, OFF_IC = 100,000,000. B = 16384.
//
// R4: wall-clock is pinned at the graph-replay floor (~6.6us across three
// kernel shapes), so optimize device time: full-SM-coverage shape
// (128 CTAs x 128 thr, best measured cold dur), exact grid (no bounds
// check), and the two long-latency cross_w gathers issued first so their
// scoreboard arms open earliest.

static constexpr int D_CAT   = 1000;
static constexpr int OFF_IC  = 100000 * D_CAT;  // 100,000,000
static constexpr int B_TOTAL = 16384;
static constexpr int THREADS = 128;

__global__ void __launch_bounds__(THREADS) wide_kernel(
    const int* __restrict__ user_id,
    const int* __restrict__ item_id,
    const int* __restrict__ category,
    const float* __restrict__ emb_user,
    const float* __restrict__ emb_item,
    const float* __restrict__ emb_cat,
    const float* __restrict__ cross_w,
    float* __restrict__ out)
{
    int b = blockIdx.x * THREADS + threadIdx.x;  // exact grid: 0..16383

    // Index loads (coalesced; independent)
    int u = __ldg(&user_id[b]);
    int i = __ldg(&item_id[b]);
    int c = __ldg(&category[b]);

    // Longest-latency gathers first (600MB table -> DRAM-resident cold)
    float xu = __ldg(&cross_w[u * D_CAT + c]);
    float xi = __ldg(&cross_w[OFF_IC + i * D_CAT + c]);
    // Small tables (L2/L1-resident)
    float wu = __ldg(&emb_user[u]);
    float wi = __ldg(&emb_item[i]);
    float wc = __ldg(&emb_cat[c]);

    out[b] = (xu + xi) + (wu + wi) + wc;
}

extern "C" void kernel_launch(void* const* d_in, const int* in_sizes, int n_in,
                              void* d_out, int out_size)
{
    const int*   user_id  = (const int*)  d_in[0];
    const int*   item_id  = (const int*)  d_in[1];
    const int*   category = (const int*)  d_in[2];
    const float* emb_user = (const float*)d_in[3];
    const float* emb_item = (const float*)d_in[4];
    const float* emb_cat  = (const float*)d_in[5];
    const float* cross_w  = (const float*)d_in[6];
    float*       out      = (float*)d_out;

    wide_kernel<<<B_TOTAL / THREADS, THREADS>>>(user_id, item_id, category,
                                                emb_user, emb_item, emb_cat,
                                                cross_w, out);
}